// round 1
// baseline (speedup 1.0000x reference)
#include <cuda_runtime.h>

#define BQ    32
#define NN    512
#define MM    512
#define DFD   64
#define NDIAG 1023          // diagonals d = 2 .. 1024 -> (d-2) in [0, 1022]
#define BIGV  1e10f

// Diagonal-major distance scratch: g_D[b][(i+j)][i] for 0-based i,j.
// 32 * 1023 * 512 floats = 67 MB (static device allocation; no cudaMalloc).
__device__ float g_D[(size_t)BQ * NDIAG * NN];

// ---------------------------------------------------------------------------
// Kernel 1: pairwise squared distances, written in anti-diagonal layout.
// Grid: (8, 8, 32) tiles of 64x64; 256 threads; 4x4 register tile per thread.
// ---------------------------------------------------------------------------
__global__ void dist_kernel(const float* __restrict__ X,
                            const float* __restrict__ Y) {
    __shared__ float sm[2 * 64 * 65];   // Xs | Ys, padded pitch 65 (bank-safe)
    float* Xs = sm;
    float* Ys = sm + 64 * 65;

    const int b  = blockIdx.z;
    const int i0 = blockIdx.y * 64;
    const int j0 = blockIdx.x * 64;
    const int tid = threadIdx.x;

    const float* Xb = X + ((size_t)b * NN + i0) * DFD;
    const float* Yb = Y + ((size_t)b * MM + j0) * DFD;

    #pragma unroll
    for (int idx = tid; idx < 64 * 64; idx += 256) {
        int r = idx >> 6, c = idx & 63;
        Xs[r * 65 + c] = Xb[r * 64 + c];
        Ys[r * 65 + c] = Yb[r * 64 + c];
    }
    __syncthreads();

    const int ti = (tid >> 4) * 4;   // row group
    const int tj = (tid & 15) * 4;   // col group

    float acc[4][4];
    #pragma unroll
    for (int u = 0; u < 4; u++)
        #pragma unroll
        for (int v = 0; v < 4; v++) acc[u][v] = 0.f;

    #pragma unroll 4
    for (int k = 0; k < DFD; k++) {
        float xa[4], yb[4];
        #pragma unroll
        for (int u = 0; u < 4; u++) xa[u] = Xs[(ti + u) * 65 + k];
        #pragma unroll
        for (int v = 0; v < 4; v++) yb[v] = Ys[(tj + v) * 65 + k];
        #pragma unroll
        for (int u = 0; u < 4; u++)
            #pragma unroll
            for (int v = 0; v < 4; v++) {
                float dd = xa[u] - yb[v];
                acc[u][v] = fmaf(dd, dd, acc[u][v]);
            }
    }
    __syncthreads();

    // Stage result tile into SMEM (pitch 66 -> conflict-free diagonal reads:
    // addr = ii*66 + (dl-ii) = 65*ii + dl, 65 = 1 mod 32).
    float* Dt = sm;   // reuse; 64*66 = 4224 floats < 8320
    #pragma unroll
    for (int u = 0; u < 4; u++)
        #pragma unroll
        for (int v = 0; v < 4; v++)
            Dt[(ti + u) * 66 + (tj + v)] = acc[u][v];
    __syncthreads();

    // Coalesced diagonal-major writeback.
    const int warp = tid >> 5, lane = tid & 31;
    const size_t base = (size_t)b * NDIAG * NN;
    for (int dl = warp; dl < 127; dl += 8) {
        int lo = dl - 63; if (lo < 0) lo = 0;
        int hi = dl;      if (hi > 63) hi = 63;
        for (int ii = lo + lane; ii <= hi; ii += 32) {
            int gi = i0 + ii;
            int gj = j0 + dl - ii;
            g_D[base + (size_t)(gi + gj) * NN + gi] = Dt[ii * 66 + (dl - ii)];
        }
    }
}

// ---------------------------------------------------------------------------
// Kernel 2: anti-diagonal wavefront soft-DTW. One CTA per batch.
// 512 threads: thread tid owns row i = tid+1. Triple-buffered diagonals in
// SMEM; own previous value kept in a register; D prefetched 2 diagonals ahead.
// ---------------------------------------------------------------------------
__global__ void __launch_bounds__(512, 1)
dp_kernel(const int* __restrict__ X_len, const int* __restrict__ Y_len,
          float* __restrict__ out) {
    __shared__ float buf[3][516];

    const int b   = blockIdx.x;
    const int tid = threadIdx.x;
    const int i   = tid + 1;                    // row index 1..512

    const int xl  = X_len[b];
    const int tot = xl + Y_len[b];              // output diagonal

    // Init: buf[0] = diagonal 0 (R[0][0]=0, rest BIG); buf[1] = diagonal 1.
    buf[0][i] = BIGV;
    buf[1][i] = BIGV;
    if (tid == 0) { buf[0][0] = 0.f; buf[1][0] = BIGV; buf[2][0] = BIGV; }
    __syncthreads();

    const float* Db = g_D + (size_t)b * NDIAG * NN + (i - 1);

    // Prefetch pipeline (depth 2): Dv0 = D for diagonal d, Dv1 = d+1.
    float Dv0 = (2 - i >= 1)              ? Db[0]   : 0.f;   // d = 2
    float Dv1 = (3 - i >= 1 && 3 - i <= MM) ? Db[NN] : 0.f;  // d = 3

    float cprev = BIGV;   // R[i][j-1]: this thread's value on previous diagonal
    int pp = 0;           // buffer index of diagonal d-2

    #pragma unroll 1
    for (int d = 2; d <= NN + MM; ++d) {
        const float Dcur = Dv0;
        Dv0 = Dv1;
        {   // prefetch D for diagonal d+2: slot (d+2-2)*NN = d*NN
            int j2 = d + 2 - i;
            Dv1 = (d + 2 <= NN + MM && j2 >= 1 && j2 <= MM)
                      ? Db[(size_t)d * NN] : 0.f;
        }

        const int pm1 = (pp + 1 == 3) ? 0 : pp + 1;
        const int pc  = (pm1 + 1 == 3) ? 0 : pm1 + 1;

        const float a  = buf[pp][i - 1];    // R[i-1][j-1]
        const float bb = buf[pm1][i - 1];   // R[i-1][j]
        const float c  = cprev;             // R[i][j-1]

        // Sort 3 values (ALU only), then 2 EX2 + 1 LG2 (MUFU).
        const float mn1 = fminf(a, bb), mx1 = fmaxf(a, bb);
        const float m   = fminf(mn1, c);
        const float mid = fminf(mx1, fmaxf(mn1, c));
        const float top = fmaxf(mx1, c);
        const float s   = 1.0f + __expf(m - mid) + __expf(m - top);

        const int  j     = d - i;
        const bool valid = (j >= 1) & (j <= MM);
        const float val  = valid ? (Dcur + m - __logf(s)) : BIGV;

        buf[pc][i] = val;
        cprev = val;
        if (tid == 0) buf[pc][0] = BIGV;    // R[0][d] border

        if (d == tot && i == xl) out[b] = val;

        pp = pm1;
        __syncthreads();
    }
}

// ---------------------------------------------------------------------------
extern "C" void kernel_launch(void* const* d_in, const int* in_sizes, int n_in,
                              void* d_out, int out_size) {
    const float* X     = (const float*)d_in[0];
    const float* Y     = (const float*)d_in[1];
    const int*   X_len = (const int*)d_in[2];
    const int*   Y_len = (const int*)d_in[3];
    float*       out   = (float*)d_out;

    dist_kernel<<<dim3(8, 8, BQ), 256>>>(X, Y);
    dp_kernel<<<BQ, 512>>>(X_len, Y_len, out);
}